// round 16
// baseline (speedup 1.0000x reference)
#include <cuda_runtime.h>
#include <cuda_fp16.h>
#include <mma.h>
using namespace nvcuda;

#define NU 50000
#define NI 50000
#define NN 100000
#define DIM 64
#define EMAX 2000000
#define FW 192              // combined feature width: 3 stacks x 64
#define FW2 96              // in half2 units
#define NB_SCAN 196         // 196*512 >= 100000
#define DSPLIT 149888       // 1171*128 : dense user/item row split (< 3*NU)
#define NA 50000            // agg0 first-half node count

typedef unsigned long long u64;

// ---------------- device scratch (static; no dynamic allocation) -------------
__device__ int     g_deg[NN];                  // neighbor count (excl. self)
__device__ float   g_dinv[NN];
__device__ int     g_rowptr[NN];
__device__ int     g_cursor[NN];
__device__ int2    g_edges[2 * EMAX];          // (src, bitcast(dinv[src]))
__device__ __half2 g_X0h[(size_t)NN * FW2];    // layer-0 input (kept for output), fp16
__device__ __half2 g_Xh[(size_t)NN * FW2];     // current layer input, fp16
__device__ __half2 g_Hh0[(size_t)NN * FW2];    // layer-0 dense output, fp16
__device__ __half2 g_Hh1[(size_t)NN * FW2];    // layer-1 dense output, fp16
__device__ int     g_partial[NB_SCAN];

__device__ __forceinline__ unsigned h2u(__half2 h) { return *reinterpret_cast<unsigned*>(&h); }

// ---- packed f32x2 helpers (Blackwell FFMA2 path) ----------------------------
__device__ __forceinline__ u64 pack2(float lo, float hi) {
    u64 r; asm("mov.b64 %0, {%1, %2};" : "=l"(r) : "f"(lo), "f"(hi)); return r;
}
__device__ __forceinline__ void unpack2(u64 a, float& lo, float& hi) {
    asm("mov.b64 {%0, %1}, %2;" : "=f"(lo), "=f"(hi) : "l"(a));
}
__device__ __forceinline__ u64 h2f2(unsigned h) {
    __half2 hh = *reinterpret_cast<__half2*>(&h);
    float2 f = __half22float2(hh);
    return pack2(f.x, f.y);
}
__device__ __forceinline__ void ffma2(u64& d, u64 a, u64 b) {   // d = a*b + d
    asm("fma.rn.f32x2 %0, %1, %2, %0;" : "+l"(d) : "l"(a), "l"(b));
}
__device__ __forceinline__ u64 add2(u64 a, u64 b) {
    u64 r; asm("add.rn.f32x2 %0, %1, %2;" : "=l"(r) : "l"(a), "l"(b)); return r;
}
__device__ __forceinline__ u64 mul2(u64 a, u64 b) {
    u64 r; asm("mul.rn.f32x2 %0, %1, %2;" : "=l"(r) : "l"(a), "l"(b)); return r;
}
__device__ __forceinline__ unsigned f2h2(u64 a) {               // pack -> half2
    float lo, hi; unpack2(a, lo, hi);
    unsigned r; asm("cvt.rn.f16x2.f32 %0, %1, %2;" : "=r"(r) : "f"(hi), "f"(lo));
    return r;
}

// ---------------- graph build ------------------------------------------------
__global__ void k_deg_zero() {
    int n = blockIdx.x * blockDim.x + threadIdx.x;
    if (n < NN) g_deg[n] = 0;
}

__global__ void k_count(const int* __restrict__ ei, int E) {
    int e = blockIdx.x * blockDim.x + threadIdx.x;
    if (e >= E) return;
    int u = ei[2 * e];
    int it = ei[2 * e + 1] + NU;
    atomicAdd(&g_deg[u], 1);
    atomicAdd(&g_deg[it], 1);
}

__global__ void k_scan1() {
    __shared__ int sh[512];
    int t = threadIdx.x;
    int idx = blockIdx.x * 512 + t;
    int v = (idx < NN) ? g_deg[idx] : 0;
    sh[t] = v;
    __syncthreads();
    for (int off = 256; off > 0; off >>= 1) {
        if (t < off) sh[t] += sh[t + off];
        __syncthreads();
    }
    if (t == 0) g_partial[blockIdx.x] = sh[0];
}

__global__ void k_scan2() {      // 256-thread single-block exclusive scan of partials
    __shared__ int sh[256];
    int t = threadIdx.x;
    int v = (t < NB_SCAN) ? g_partial[t] : 0;
    sh[t] = v;
    __syncthreads();
    for (int off = 1; off < 256; off <<= 1) {
        int x = (t >= off) ? sh[t - off] : 0;
        __syncthreads();
        sh[t] += x;
        __syncthreads();
    }
    if (t < NB_SCAN) g_partial[t] = sh[t] - v;
}

__global__ void k_scan3() {   // exclusive scan + dinv (fused)
    __shared__ int sh[512];
    int t = threadIdx.x;
    int idx = blockIdx.x * 512 + t;
    int v = (idx < NN) ? g_deg[idx] : 0;
    sh[t] = v;
    __syncthreads();
    for (int off = 1; off < 512; off <<= 1) {
        int x = (t >= off) ? sh[t - off] : 0;
        __syncthreads();
        sh[t] += x;
        __syncthreads();
    }
    if (idx < NN) {
        int excl = g_partial[blockIdx.x] + sh[t] - v;
        g_rowptr[idx] = excl;
        g_cursor[idx] = excl;
        g_dinv[idx] = rsqrtf((float)(v + 1));   // +1 = self loop
    }
}

__global__ void k_fill(const int* __restrict__ ei, int E) {
    int e = blockIdx.x * blockDim.x + threadIdx.x;
    if (e >= E) return;
    int u = ei[2 * e];
    int it = ei[2 * e + 1] + NU;
    float du = g_dinv[u];
    float di = g_dinv[it];
    int p1 = atomicAdd(&g_cursor[it], 1);   // dst = item, src = user
    g_edges[p1] = make_int2(u, __float_as_int(du));
    int p2 = atomicAdd(&g_cursor[u], 1);    // dst = user, src = item
    g_edges[p2] = make_int2(it, __float_as_int(di));
}

// ---------------- init combined X0 / X (both fp16) ---------------------------
__global__ void k_initX(const float* __restrict__ ue, const float* __restrict__ uev,
                        const float* __restrict__ uet, const float* __restrict__ ie) {
    int i = blockIdx.x * blockDim.x + threadIdx.x;     // over NU*32 (half2 cols)
    if (i >= NU * 32) return;
    int u = i >> 5;
    int c2 = i & 31;
    float2 a = ((const float2*)ue)[i];
    float2 b = ((const float2*)uev)[i];
    float2 d = ((const float2*)uet)[i];
    float2 e = ((const float2*)ie)[i];
    size_t ub = (size_t)u * FW2 + c2;
    __half2 ha = __floats2half2_rn(a.x, a.y);
    __half2 hb = __floats2half2_rn(b.x, b.y);
    __half2 hd = __floats2half2_rn(d.x, d.y);
    __half2 he = __floats2half2_rn(e.x, e.y);
    g_Xh[ub] = ha;       g_X0h[ub] = ha;
    g_Xh[ub + 32] = hb;  g_X0h[ub + 32] = hb;
    g_Xh[ub + 64] = hd;  g_X0h[ub + 64] = hd;
    size_t ib = (size_t)(NU + u) * FW2 + c2;
    g_Xh[ib] = he;       g_X0h[ib] = he;
}

// ---------------- projection GEMM (HMMA, register-prefetch pipelined) --------
// C(Mx64) = A(MxK) @ W(64xK)^T + bias ->  Xh + X0h fp16 item slices
// OUT_MODE 0: col offset 64 (v) ; OUT_MODE 1: col offset 128 (t)
#define LDA 40    // smem ld in halves
#define LDC2 20   // epilogue staging ld in floats (16 cols + pad)

template <int OUT_MODE>
__global__ void __launch_bounds__(256) k_wgemm_proj(const float* __restrict__ A, int M, int K,
                                                    const float* __restrict__ W,
                                                    const float* __restrict__ bias) {
    __shared__ __align__(16) char raw[128 * LDA * 2 + 64 * LDA * 2];   // 15360 B
    half*  As = (half*)raw;                   // [128][LDA]
    half*  Ws = (half*)(raw + 128 * LDA * 2); // [64][LDA]
    float* Cs = (float*)raw;                  // [128][LDC2] (overlaps A after K loop)

    int tid = threadIdx.x;
    int warp = tid >> 5;
    int rowBase = blockIdx.x * 128;

    wmma::fragment<wmma::accumulator, 16, 16, 16, float> acc[4];
#pragma unroll
    for (int nf = 0; nf < 4; ++nf) wmma::fill_fragment(acc[nf], 0.f);

    int lr = tid >> 1;               // 0..127 (A row)
    int lk = (tid & 1) * 16;         // 0/16   (A k base)
    bool rowOK = (rowBase + lr) < M;
    const float* Arow = A + (size_t)(rowBase + lr) * K + lk;

    float4 ra[4], rw[2];
    const float4 z4 = make_float4(0.f, 0.f, 0.f, 0.f);

#define LOAD_TILES(k0_)                                                     \
    {                                                                       \
        _Pragma("unroll")                                                   \
        for (int q = 0; q < 4; ++q)                                         \
            ra[q] = rowOK ? *(const float4*)(Arow + (k0_) + q * 4) : z4;    \
        _Pragma("unroll")                                                   \
        for (int it = 0; it < 2; ++it) {                                    \
            int f = tid + it * 256;                                         \
            int c = f >> 3;                                                 \
            int kq = (f & 7) * 4;                                           \
            rw[it] = *(const float4*)(W + (size_t)c * K + (k0_) + kq);      \
        }                                                                   \
    }

    LOAD_TILES(0);
    for (int k0 = 0; k0 < K; k0 += 32) {
        {
            half* da = As + lr * LDA + lk;
#pragma unroll
            for (int q = 0; q < 4; ++q) {
                *(half2*)(da + q * 4)     = __floats2half2_rn(ra[q].x, ra[q].y);
                *(half2*)(da + q * 4 + 2) = __floats2half2_rn(ra[q].z, ra[q].w);
            }
#pragma unroll
            for (int it = 0; it < 2; ++it) {
                int f = tid + it * 256;
                int c = f >> 3;
                int kq = (f & 7) * 4;
                half* dw = Ws + c * LDA + kq;
                *(half2*)(dw)     = __floats2half2_rn(rw[it].x, rw[it].y);
                *(half2*)(dw + 2) = __floats2half2_rn(rw[it].z, rw[it].w);
            }
        }
        __syncthreads();
        if (k0 + 32 < K) LOAD_TILES(k0 + 32);   // prefetch next while mma runs
#pragma unroll
        for (int kk = 0; kk < 32; kk += 16) {
            wmma::fragment<wmma::matrix_a, 16, 16, 16, half, wmma::row_major> af;
            wmma::load_matrix_sync(af, As + (warp * 16) * LDA + kk, LDA);
#pragma unroll
            for (int nf = 0; nf < 4; ++nf) {
                wmma::fragment<wmma::matrix_b, 16, 16, 16, half, wmma::col_major> bf;
                wmma::load_matrix_sync(bf, Ws + (nf * 16) * LDA + kk, LDA);
                wmma::mma_sync(acc[nf], af, bf, acc[nf]);
            }
        }
        __syncthreads();
    }

    // epilogue, staged 16 cols at a time through small smem
    int r = tid >> 1;
    int c8 = (tid & 1) * 8;
    int gr = rowBase + r;
    int coff = (OUT_MODE == 0) ? 64 : 128;
#pragma unroll
    for (int nf = 0; nf < 4; ++nf) {
        wmma::store_matrix_sync(Cs + (warp * 16) * LDC2, acc[nf], LDC2, wmma::mem_row_major);
        __syncthreads();
        if (gr < M) {
            const float* src = Cs + r * LDC2 + c8;
            int cbase = nf * 16 + c8;
            __half2 h[4];
#pragma unroll
            for (int q = 0; q < 4; ++q) {
                float vx = src[2 * q]     + __ldg(&bias[cbase + 2 * q]);
                float vy = src[2 * q + 1] + __ldg(&bias[cbase + 2 * q + 1]);
                h[q] = __floats2half2_rn(vx, vy);
            }
            uint4 u = make_uint4(h2u(h[0]), h2u(h[1]), h2u(h[2]), h2u(h[3]));
            size_t o = (size_t)(NU + gr) * FW2 + ((coff + cbase) >> 1);
            *(uint4*)(g_Xh + o)  = u;
            *(uint4*)(g_X0h + o) = u;
        }
        __syncthreads();
    }
}

// ---------------- dense layer GEMM: H = X @ W.T (fp16 in, fp16 out) ----------
// A = g_Xh viewed as [3*NN][64] halves; rows [rowStart, ...) bounded by grid
// HBUF selects the output buffer (0: g_Hh0, 1: g_Hh1)
#define LDH 72   // smem ld in halves

template <int HBUF>
__global__ void __launch_bounds__(256) k_wgemm_dense(const float* __restrict__ W, int rowStart) {
    const int M = 3 * NN;
    __half2* Hout = (HBUF == 0) ? g_Hh0 : g_Hh1;
    __shared__ __align__(16) char raw[128 * LDH * 2 + 64 * LDH * 2];   // 27648 B
    half*  As = (half*)raw;                   // [128][LDH]
    half*  Ws = (half*)(raw + 128 * LDH * 2); // [64][LDH]
    float* Cs = (float*)raw;                  // [128][LDC2]

    int tid = threadIdx.x;
    int warp = tid >> 5;
    int rowBase = rowStart + blockIdx.x * 128;
    const half* Ah = (const half*)g_Xh;

#pragma unroll
    for (int it = 0; it < 4; ++it) {
        int c = tid + it * 256;         // 0..1023
        int r = c >> 3;
        int o = (c & 7) * 8;            // half offset
        int gr = rowBase + r;
        uint4 v = make_uint4(0, 0, 0, 0);
        if (gr < M) v = *(const uint4*)(Ah + (size_t)gr * 64 + o);
        *(uint4*)(As + r * LDH + o) = v;
    }
    {
        int c = tid >> 2;
        int seg = (tid & 3) * 16;
        const float* wsrc = W + (size_t)c * 64 + seg;
        half* dw = Ws + c * LDH + seg;
#pragma unroll
        for (int q = 0; q < 4; ++q) {
            float4 v = *(const float4*)(wsrc + q * 4);
            *(half2*)(dw + q * 4)     = __floats2half2_rn(v.x, v.y);
            *(half2*)(dw + q * 4 + 2) = __floats2half2_rn(v.z, v.w);
        }
    }
    __syncthreads();

    wmma::fragment<wmma::accumulator, 16, 16, 16, float> acc[4];
#pragma unroll
    for (int nf = 0; nf < 4; ++nf) wmma::fill_fragment(acc[nf], 0.f);
#pragma unroll
    for (int kk = 0; kk < 64; kk += 16) {
        wmma::fragment<wmma::matrix_a, 16, 16, 16, half, wmma::row_major> af;
        wmma::load_matrix_sync(af, As + (warp * 16) * LDH + kk, LDH);
#pragma unroll
        for (int nf = 0; nf < 4; ++nf) {
            wmma::fragment<wmma::matrix_b, 16, 16, 16, half, wmma::col_major> bf;
            wmma::load_matrix_sync(bf, Ws + (nf * 16) * LDH + kk, LDH);
            wmma::mma_sync(acc[nf], af, bf, acc[nf]);
        }
    }
    __syncthreads();

    int r = tid >> 1;
    int c8 = (tid & 1) * 8;
    int gr = rowBase + r;
#pragma unroll
    for (int nf = 0; nf < 4; ++nf) {
        wmma::store_matrix_sync(Cs + (warp * 16) * LDC2, acc[nf], LDC2, wmma::mem_row_major);
        __syncthreads();
        if (gr < M) {
            const float* src = Cs + r * LDC2 + c8;
            __half2 h[4];
#pragma unroll
            for (int q = 0; q < 4; ++q)
                h[q] = __floats2half2_rn(src[2 * q], src[2 * q + 1]);
            uint4 u = make_uint4(h2u(h[0]), h2u(h[1]), h2u(h[2]), h2u(h[3]));
            *(uint4*)(Hout + (size_t)gr * 32 + ((nf * 16 + c8) >> 1)) = u;
        }
        __syncthreads();
    }
}

// ---------------- aggregation (vectorized: LDG.128 gather + FFMA2) -----------
// Lane L (<24) owns halves [8L, 8L+8) of the 192-wide node row.
// x_new = dinv[dst]*(sum w*H[src] + dinv[dst]*H[dst]) + b
// FINAL=0: reads g_Hh0, Xh = x_new     (node range [nodeStart, nodeStart+nodeCnt))
// FINAL=1: reads g_Hh1, out[section] = (X0 + X1 + x_new)/3
#define AGG_V(w2_, v_)                              \
    {                                               \
        ffma2(a0, (w2_), h2f2((v_).x));             \
        ffma2(a1, (w2_), h2f2((v_).y));             \
        ffma2(a2, (w2_), h2f2((v_).z));             \
        ffma2(a3, (w2_), h2f2((v_).w));             \
    }

template <int FINAL>
__global__ void __launch_bounds__(256) k_agg(const float* __restrict__ bias,
                                             float* __restrict__ out,
                                             int nodeStart, int nodeCnt) {
    int warp = threadIdx.x >> 5;
    int lane = threadIdx.x & 31;
    int nidx = blockIdx.x * 8 + warp;
    if (nidx >= nodeCnt) return;
    int node = nodeStart + nidx;

    const uint4* Hv = (const uint4*)((FINAL == 0) ? g_Hh0 : g_Hh1);  // 24 uint4/row
    int ll = (lane < 24) ? lane : 0;          // clamp for safe addresses

    float dn = g_dinv[node];
    u64 dn2 = pack2(dn, dn);
    size_t rbase = (size_t)node * 24;

    // accumulators: 4 packed f32x2 = 8 floats = 8 halves of this lane
    u64 a0 = 0, a1 = 0, a2 = 0, a3 = 0;

    // self-loop (weight dinv; outer dinv applied at end -> dinv^2)
    {
        uint4 hv = __ldg(&Hv[rbase + ll]);
        AGG_V(dn2, hv);
    }

    int p = g_rowptr[node];
    int cnt = g_deg[node];

    int j = 0;
    for (; j + 4 <= cnt; j += 4) {
        int2 e0 = __ldg(&g_edges[p + j]);
        int2 e1 = __ldg(&g_edges[p + j + 1]);
        int2 e2 = __ldg(&g_edges[p + j + 2]);
        int2 e3 = __ldg(&g_edges[p + j + 3]);
        uint4 v0 = __ldg(&Hv[(size_t)e0.x * 24 + ll]);
        uint4 v1 = __ldg(&Hv[(size_t)e1.x * 24 + ll]);
        uint4 v2 = __ldg(&Hv[(size_t)e2.x * 24 + ll]);
        uint4 v3 = __ldg(&Hv[(size_t)e3.x * 24 + ll]);
        u64 w0 = pack2(__int_as_float(e0.y), __int_as_float(e0.y));
        u64 w1 = pack2(__int_as_float(e1.y), __int_as_float(e1.y));
        u64 w2 = pack2(__int_as_float(e2.y), __int_as_float(e2.y));
        u64 w3 = pack2(__int_as_float(e3.y), __int_as_float(e3.y));
        AGG_V(w0, v0); AGG_V(w1, v1); AGG_V(w2, v2); AGG_V(w3, v3);
    }
    for (; j < cnt; ++j) {
        int2 e = __ldg(&g_edges[p + j]);
        uint4 v = __ldg(&Hv[(size_t)e.x * 24 + ll]);
        u64 w = pack2(__int_as_float(e.y), __int_as_float(e.y));
        AGG_V(w, v);
    }

    // bias for this lane's 8 columns (same bias across the 3 stacks)
    int c0 = (lane & 7) * 8;                      // column base within stack
    float4 bA = __ldg((const float4*)(bias + c0));
    float4 bB = __ldg((const float4*)(bias + c0 + 4));
    u64 b0p = pack2(bA.x, bA.y), b1p = pack2(bA.z, bA.w);
    u64 b2p = pack2(bB.x, bB.y), b3p = pack2(bB.z, bB.w);

    // o = acc*dn + b
    u64 o0 = b0p, o1 = b1p, o2 = b2p, o3 = b3p;
    ffma2(o0, a0, dn2); ffma2(o1, a1, dn2); ffma2(o2, a2, dn2); ffma2(o3, a3, dn2);

    if (FINAL) {
        if (lane < 24) {
            const uint4* X0v = (const uint4*)g_X0h;
            const uint4* X1v = (const uint4*)g_Xh;
            uint4 x0 = __ldg(&X0v[rbase + lane]);
            uint4 x1 = __ldg(&X1v[rbase + lane]);
            u64 i3 = pack2(1.f / 3.f, 1.f / 3.f);
            u64 s0 = mul2(add2(add2(h2f2(x0.x), h2f2(x1.x)), o0), i3);
            u64 s1 = mul2(add2(add2(h2f2(x0.y), h2f2(x1.y)), o1), i3);
            u64 s2 = mul2(add2(add2(h2f2(x0.z), h2f2(x1.z)), o2), i3);
            u64 s3 = mul2(add2(add2(h2f2(x0.w), h2f2(x1.w)), o3), i3);
            int itm = (node >= NU) ? 1 : 0;
            int r = node - itm * NU;
            int st = lane >> 3;                   // stack 0..2
            float* dst = out + (size_t)(2 * st + itm) * (NU * 64) + (size_t)r * 64 + c0;
            float4 oA, oB;
            unpack2(s0, oA.x, oA.y); unpack2(s1, oA.z, oA.w);
            unpack2(s2, oB.x, oB.y); unpack2(s3, oB.z, oB.w);
            __stcs((float4*)dst, oA);
            __stcs((float4*)(dst + 4), oB);
        }
    } else {
        if (lane < 24) {
            uint4 hx = make_uint4(f2h2(o0), f2h2(o1), f2h2(o2), f2h2(o3));
            ((uint4*)g_Xh)[rbase + lane] = hx;
        }
    }
}

// ---------------- launch ------------------------------------------------------
extern "C" void kernel_launch(void* const* d_in, const int* in_sizes, int n_in,
                              void* d_out, int out_size) {
    const int* ei = (const int*)d_in[0];
    const float* v_feat = (const float*)d_in[1];
    const float* t_feat = (const float*)d_in[2];
    const float* user_emb = (const float*)d_in[3];
    const float* item_emb = (const float*)d_in[4];
    const float* user_emb_v = (const float*)d_in[5];
    const float* user_emb_t = (const float*)d_in[6];
    const float* W_v = (const float*)d_in[7];
    const float* b_v = (const float*)d_in[8];
    const float* W_t = (const float*)d_in[9];
    const float* b_t = (const float*)d_in[10];
    const float* W0 = (const float*)d_in[11];
    const float* b0 = (const float*)d_in[12];
    const float* W1 = (const float*)d_in[13];
    const float* b1 = (const float*)d_in[14];
    float* out = (float*)d_out;

    int E = in_sizes[0] / 2;
    if (E > EMAX) E = EMAX;

    // lazy infra (created on the uncaptured correctness call; reused thereafter)
    static cudaStream_t sT = nullptr, sG = nullptr;
    static cudaEvent_t evRoot = nullptr, evT = nullptr, evG = nullptr;
    static cudaEvent_t evA0A = nullptr, evD1A = nullptr;
    if (sT == nullptr) {
        cudaStreamCreateWithFlags(&sT, cudaStreamNonBlocking);
        cudaStreamCreateWithFlags(&sG, cudaStreamNonBlocking);
        cudaEventCreateWithFlags(&evRoot, cudaEventDisableTiming);
        cudaEventCreateWithFlags(&evT, cudaEventDisableTiming);
        cudaEventCreateWithFlags(&evG, cudaEventDisableTiming);
        cudaEventCreateWithFlags(&evA0A, cudaEventDisableTiming);
        cudaEventCreateWithFlags(&evD1A, cudaEventDisableTiming);
    }

    // fork side streams off the main (capture) stream
    cudaEventRecord(evRoot, 0);
    cudaStreamWaitEvent(sG, evRoot, 0);
    cudaStreamWaitEvent(sT, evRoot, 0);

    // sG: graph build (independent of everything else)
    k_deg_zero<<<(NN + 255) / 256, 256, 0, sG>>>();
    k_count<<<(E + 255) / 256, 256, 0, sG>>>(ei, E);
    k_scan1<<<NB_SCAN, 512, 0, sG>>>();
    k_scan2<<<1, 256, 0, sG>>>();
    k_scan3<<<NB_SCAN, 512, 0, sG>>>();
    k_fill<<<(E + 255) / 256, 256, 0, sG>>>(ei, E);
    cudaEventRecord(evG, sG);

    // sT: initX -> t projection -> dense-L0 user rows (all only need initX)
    k_initX<<<(NU * 32 + 255) / 256, 256, 0, sT>>>(user_emb, user_emb_v, user_emb_t, item_emb);
    k_wgemm_proj<1><<<(NU + 127) / 128, 256, 0, sT>>>(t_feat, NU, 768, W_t, b_t);
    k_wgemm_dense<0><<<DSPLIT / 128, 256, 0, sT>>>(W0, 0);
    cudaEventRecord(evT, sT);

    // main: v projection (big one) runs immediately
    k_wgemm_proj<0><<<(NU + 127) / 128, 256>>>(v_feat, NU, 2048, W_v, b_v);

    // join sT, then dense-L0 item rows
    cudaStreamWaitEvent(0, evT, 0);
    k_wgemm_dense<0><<<(3 * NN - DSPLIT + 127) / 128, 256>>>(W0, DSPLIT);

    // join graph build, then aggregate layer 0 (first half: nodes [0, NA))
    cudaStreamWaitEvent(0, evG, 0);
    k_agg<0><<<(NA + 7) / 8, 256>>>(b0, nullptr, 0, NA);
    cudaEventRecord(evA0A, 0);

    // sT: dense-L1 part A (rows [0, DSPLIT) -> nodes < 50000, final after agg0 A;
    //     writes g_Hh1 — no conflict with agg0 part B which reads g_Hh0)
    cudaStreamWaitEvent(sT, evA0A, 0);
    k_wgemm_dense<1><<<DSPLIT / 128, 256, 0, sT>>>(W1, 0);
    cudaEventRecord(evD1A, sT);

    // main: agg layer 0 second half (nodes [NA, NN)) — overlaps dense-L1 part A
    k_agg<0><<<(NN - NA + 7) / 8, 256>>>(b0, nullptr, NA, NN - NA);

    // join, dense-L1 part B, then final aggregation (fused output)
    cudaStreamWaitEvent(0, evD1A, 0);
    k_wgemm_dense<1><<<(3 * NN - DSPLIT + 127) / 128, 256>>>(W1, DSPLIT);
    k_agg<1><<<(NN + 7) / 8, 256>>>(b1, out, 0, NN);
}

// round 17
// speedup vs baseline: 1.1470x; 1.1470x over previous
#include <cuda_runtime.h>
#include <cuda_fp16.h>
#include <mma.h>
using namespace nvcuda;

#define NU 50000
#define NI 50000
#define NN 100000
#define DIM 64
#define EMAX 2000000
#define FW 192              // combined feature width: 3 stacks x 64
#define FW2 96              // in half2 units
#define NB_SCAN 196         // 196*512 >= 100000
#define DSPLIT 149888       // 1171*128 : dense user/item row split (< 3*NU)
#define NA 50000            // agg0 first-half node count

// ---------------- device scratch (static; no dynamic allocation) -------------
__device__ int     g_deg[NN];                  // neighbor count (excl. self)
__device__ float   g_dinv[NN];
__device__ int     g_rowptr[NN];
__device__ int     g_cursor[NN];
__device__ int2    g_edges[2 * EMAX];          // (src, bitcast(dinv[src]))
__device__ __half2 g_X0h[(size_t)NN * FW2];    // layer-0 input (kept for output), fp16
__device__ __half2 g_Xh[(size_t)NN * FW2];     // current layer input, fp16
__device__ __half2 g_Hh0[(size_t)NN * FW2];    // layer-0 dense output, fp16
__device__ __half2 g_Hh1[(size_t)NN * FW2];    // layer-1 dense output, fp16
__device__ int     g_partial[NB_SCAN];

__device__ __forceinline__ unsigned h2u(__half2 h) { return *reinterpret_cast<unsigned*>(&h); }

// ---------------- graph build ------------------------------------------------
__global__ void k_deg_zero() {
    int n = blockIdx.x * blockDim.x + threadIdx.x;
    if (n < NN) g_deg[n] = 0;
}

__global__ void k_count(const int* __restrict__ ei, int E) {
    int e = blockIdx.x * blockDim.x + threadIdx.x;
    if (e >= E) return;
    int u = ei[2 * e];
    int it = ei[2 * e + 1] + NU;
    atomicAdd(&g_deg[u], 1);
    atomicAdd(&g_deg[it], 1);
}

__global__ void k_scan1() {
    __shared__ int sh[512];
    int t = threadIdx.x;
    int idx = blockIdx.x * 512 + t;
    int v = (idx < NN) ? g_deg[idx] : 0;
    sh[t] = v;
    __syncthreads();
    for (int off = 256; off > 0; off >>= 1) {
        if (t < off) sh[t] += sh[t + off];
        __syncthreads();
    }
    if (t == 0) g_partial[blockIdx.x] = sh[0];
}

__global__ void k_scan2() {      // 256-thread single-block exclusive scan of partials
    __shared__ int sh[256];
    int t = threadIdx.x;
    int v = (t < NB_SCAN) ? g_partial[t] : 0;
    sh[t] = v;
    __syncthreads();
    for (int off = 1; off < 256; off <<= 1) {
        int x = (t >= off) ? sh[t - off] : 0;
        __syncthreads();
        sh[t] += x;
        __syncthreads();
    }
    if (t < NB_SCAN) g_partial[t] = sh[t] - v;
}

__global__ void k_scan3() {   // exclusive scan + dinv (fused)
    __shared__ int sh[512];
    int t = threadIdx.x;
    int idx = blockIdx.x * 512 + t;
    int v = (idx < NN) ? g_deg[idx] : 0;
    sh[t] = v;
    __syncthreads();
    for (int off = 1; off < 512; off <<= 1) {
        int x = (t >= off) ? sh[t - off] : 0;
        __syncthreads();
        sh[t] += x;
        __syncthreads();
    }
    if (idx < NN) {
        int excl = g_partial[blockIdx.x] + sh[t] - v;
        g_rowptr[idx] = excl;
        g_cursor[idx] = excl;
        g_dinv[idx] = rsqrtf((float)(v + 1));   // +1 = self loop
    }
}

__global__ void k_fill(const int* __restrict__ ei, int E) {
    int e = blockIdx.x * blockDim.x + threadIdx.x;
    if (e >= E) return;
    int u = ei[2 * e];
    int it = ei[2 * e + 1] + NU;
    float du = g_dinv[u];
    float di = g_dinv[it];
    int p1 = atomicAdd(&g_cursor[it], 1);   // dst = item, src = user
    g_edges[p1] = make_int2(u, __float_as_int(du));
    int p2 = atomicAdd(&g_cursor[u], 1);    // dst = user, src = item
    g_edges[p2] = make_int2(it, __float_as_int(di));
}

// ---------------- init combined X0 / X (both fp16) ---------------------------
__global__ void k_initX(const float* __restrict__ ue, const float* __restrict__ uev,
                        const float* __restrict__ uet, const float* __restrict__ ie) {
    int i = blockIdx.x * blockDim.x + threadIdx.x;     // over NU*32 (half2 cols)
    if (i >= NU * 32) return;
    int u = i >> 5;
    int c2 = i & 31;
    float2 a = ((const float2*)ue)[i];
    float2 b = ((const float2*)uev)[i];
    float2 d = ((const float2*)uet)[i];
    float2 e = ((const float2*)ie)[i];
    size_t ub = (size_t)u * FW2 + c2;
    __half2 ha = __floats2half2_rn(a.x, a.y);
    __half2 hb = __floats2half2_rn(b.x, b.y);
    __half2 hd = __floats2half2_rn(d.x, d.y);
    __half2 he = __floats2half2_rn(e.x, e.y);
    g_Xh[ub] = ha;       g_X0h[ub] = ha;
    g_Xh[ub + 32] = hb;  g_X0h[ub + 32] = hb;
    g_Xh[ub + 64] = hd;  g_X0h[ub + 64] = hd;
    size_t ib = (size_t)(NU + u) * FW2 + c2;
    g_Xh[ib] = he;       g_X0h[ib] = he;
}

// ---------------- projection GEMM (HMMA, register-prefetch pipelined) --------
// C(Mx64) = A(MxK) @ W(64xK)^T + bias ->  Xh + X0h fp16 item slices
// OUT_MODE 0: col offset 64 (v) ; OUT_MODE 1: col offset 128 (t)
#define LDA 40    // smem ld in halves
#define LDC2 20   // epilogue staging ld in floats (16 cols + pad)

template <int OUT_MODE>
__global__ void __launch_bounds__(256) k_wgemm_proj(const float* __restrict__ A, int M, int K,
                                                    const float* __restrict__ W,
                                                    const float* __restrict__ bias) {
    __shared__ __align__(16) char raw[128 * LDA * 2 + 64 * LDA * 2];   // 15360 B
    half*  As = (half*)raw;                   // [128][LDA]
    half*  Ws = (half*)(raw + 128 * LDA * 2); // [64][LDA]
    float* Cs = (float*)raw;                  // [128][LDC2] (overlaps A after K loop)

    int tid = threadIdx.x;
    int warp = tid >> 5;
    int rowBase = blockIdx.x * 128;

    wmma::fragment<wmma::accumulator, 16, 16, 16, float> acc[4];
#pragma unroll
    for (int nf = 0; nf < 4; ++nf) wmma::fill_fragment(acc[nf], 0.f);

    int lr = tid >> 1;               // 0..127 (A row)
    int lk = (tid & 1) * 16;         // 0/16   (A k base)
    bool rowOK = (rowBase + lr) < M;
    const float* Arow = A + (size_t)(rowBase + lr) * K + lk;

    float4 ra[4], rw[2];
    const float4 z4 = make_float4(0.f, 0.f, 0.f, 0.f);

#define LOAD_TILES(k0_)                                                     \
    {                                                                       \
        _Pragma("unroll")                                                   \
        for (int q = 0; q < 4; ++q)                                         \
            ra[q] = rowOK ? *(const float4*)(Arow + (k0_) + q * 4) : z4;    \
        _Pragma("unroll")                                                   \
        for (int it = 0; it < 2; ++it) {                                    \
            int f = tid + it * 256;                                         \
            int c = f >> 3;                                                 \
            int kq = (f & 7) * 4;                                           \
            rw[it] = *(const float4*)(W + (size_t)c * K + (k0_) + kq);      \
        }                                                                   \
    }

    LOAD_TILES(0);
    for (int k0 = 0; k0 < K; k0 += 32) {
        {
            half* da = As + lr * LDA + lk;
#pragma unroll
            for (int q = 0; q < 4; ++q) {
                *(half2*)(da + q * 4)     = __floats2half2_rn(ra[q].x, ra[q].y);
                *(half2*)(da + q * 4 + 2) = __floats2half2_rn(ra[q].z, ra[q].w);
            }
#pragma unroll
            for (int it = 0; it < 2; ++it) {
                int f = tid + it * 256;
                int c = f >> 3;
                int kq = (f & 7) * 4;
                half* dw = Ws + c * LDA + kq;
                *(half2*)(dw)     = __floats2half2_rn(rw[it].x, rw[it].y);
                *(half2*)(dw + 2) = __floats2half2_rn(rw[it].z, rw[it].w);
            }
        }
        __syncthreads();
        if (k0 + 32 < K) LOAD_TILES(k0 + 32);   // prefetch next while mma runs
#pragma unroll
        for (int kk = 0; kk < 32; kk += 16) {
            wmma::fragment<wmma::matrix_a, 16, 16, 16, half, wmma::row_major> af;
            wmma::load_matrix_sync(af, As + (warp * 16) * LDA + kk, LDA);
#pragma unroll
            for (int nf = 0; nf < 4; ++nf) {
                wmma::fragment<wmma::matrix_b, 16, 16, 16, half, wmma::col_major> bf;
                wmma::load_matrix_sync(bf, Ws + (nf * 16) * LDA + kk, LDA);
                wmma::mma_sync(acc[nf], af, bf, acc[nf]);
            }
        }
        __syncthreads();
    }

    // epilogue, staged 16 cols at a time through small smem
    int r = tid >> 1;
    int c8 = (tid & 1) * 8;
    int gr = rowBase + r;
    int coff = (OUT_MODE == 0) ? 64 : 128;
#pragma unroll
    for (int nf = 0; nf < 4; ++nf) {
        wmma::store_matrix_sync(Cs + (warp * 16) * LDC2, acc[nf], LDC2, wmma::mem_row_major);
        __syncthreads();
        if (gr < M) {
            const float* src = Cs + r * LDC2 + c8;
            int cbase = nf * 16 + c8;
            __half2 h[4];
#pragma unroll
            for (int q = 0; q < 4; ++q) {
                float vx = src[2 * q]     + __ldg(&bias[cbase + 2 * q]);
                float vy = src[2 * q + 1] + __ldg(&bias[cbase + 2 * q + 1]);
                h[q] = __floats2half2_rn(vx, vy);
            }
            uint4 u = make_uint4(h2u(h[0]), h2u(h[1]), h2u(h[2]), h2u(h[3]));
            size_t o = (size_t)(NU + gr) * FW2 + ((coff + cbase) >> 1);
            *(uint4*)(g_Xh + o)  = u;
            *(uint4*)(g_X0h + o) = u;
        }
        __syncthreads();
    }
}

// ---------------- dense layer GEMM: H = X @ W.T (fp16 in, fp16 out) ----------
// A = g_Xh viewed as [3*NN][64] halves; rows [rowStart, ...) bounded by grid
// HBUF selects the output buffer (0: g_Hh0, 1: g_Hh1)
#define LDH 72   // smem ld in halves

template <int HBUF>
__global__ void __launch_bounds__(256) k_wgemm_dense(const float* __restrict__ W, int rowStart) {
    const int M = 3 * NN;
    __half2* Hout = (HBUF == 0) ? g_Hh0 : g_Hh1;
    __shared__ __align__(16) char raw[128 * LDH * 2 + 64 * LDH * 2];   // 27648 B
    half*  As = (half*)raw;                   // [128][LDH]
    half*  Ws = (half*)(raw + 128 * LDH * 2); // [64][LDH]
    float* Cs = (float*)raw;                  // [128][LDC2]

    int tid = threadIdx.x;
    int warp = tid >> 5;
    int rowBase = rowStart + blockIdx.x * 128;
    const half* Ah = (const half*)g_Xh;

#pragma unroll
    for (int it = 0; it < 4; ++it) {
        int c = tid + it * 256;         // 0..1023
        int r = c >> 3;
        int o = (c & 7) * 8;            // half offset
        int gr = rowBase + r;
        uint4 v = make_uint4(0, 0, 0, 0);
        if (gr < M) v = *(const uint4*)(Ah + (size_t)gr * 64 + o);
        *(uint4*)(As + r * LDH + o) = v;
    }
    {
        int c = tid >> 2;
        int seg = (tid & 3) * 16;
        const float* wsrc = W + (size_t)c * 64 + seg;
        half* dw = Ws + c * LDH + seg;
#pragma unroll
        for (int q = 0; q < 4; ++q) {
            float4 v = *(const float4*)(wsrc + q * 4);
            *(half2*)(dw + q * 4)     = __floats2half2_rn(v.x, v.y);
            *(half2*)(dw + q * 4 + 2) = __floats2half2_rn(v.z, v.w);
        }
    }
    __syncthreads();

    wmma::fragment<wmma::accumulator, 16, 16, 16, float> acc[4];
#pragma unroll
    for (int nf = 0; nf < 4; ++nf) wmma::fill_fragment(acc[nf], 0.f);
#pragma unroll
    for (int kk = 0; kk < 64; kk += 16) {
        wmma::fragment<wmma::matrix_a, 16, 16, 16, half, wmma::row_major> af;
        wmma::load_matrix_sync(af, As + (warp * 16) * LDH + kk, LDH);
#pragma unroll
        for (int nf = 0; nf < 4; ++nf) {
            wmma::fragment<wmma::matrix_b, 16, 16, 16, half, wmma::col_major> bf;
            wmma::load_matrix_sync(bf, Ws + (nf * 16) * LDH + kk, LDH);
            wmma::mma_sync(acc[nf], af, bf, acc[nf]);
        }
    }
    __syncthreads();

    int r = tid >> 1;
    int c8 = (tid & 1) * 8;
    int gr = rowBase + r;
#pragma unroll
    for (int nf = 0; nf < 4; ++nf) {
        wmma::store_matrix_sync(Cs + (warp * 16) * LDC2, acc[nf], LDC2, wmma::mem_row_major);
        __syncthreads();
        if (gr < M) {
            const float* src = Cs + r * LDC2 + c8;
            __half2 h[4];
#pragma unroll
            for (int q = 0; q < 4; ++q)
                h[q] = __floats2half2_rn(src[2 * q], src[2 * q + 1]);
            uint4 u = make_uint4(h2u(h[0]), h2u(h[1]), h2u(h[2]), h2u(h[3]));
            *(uint4*)(Hout + (size_t)gr * 32 + ((nf * 16 + c8) >> 1)) = u;
        }
        __syncthreads();
    }
}

// ---------------- aggregation over fp16 H (scalar half2 form — proven) -------
// x_new = dinv[dst]*(sum w*H[src] + dinv[dst]*H[dst]) + b
// FINAL=0: reads g_Hh0, Xh = x_new     (node range [nodeStart, nodeStart+nodeCnt))
// FINAL=1: reads g_Hh1, out[section] = (X0 + X1 + x_new)/3  (streaming stores)
#define AGG_STEP(e)                                                     \
    {                                                                   \
        int s_ = (e).x;                                                 \
        float w_ = __int_as_float((e).y);                               \
        size_t sb_ = (size_t)s_ * FW2 + lane;                           \
        float2 v0_ = __half22float2(__ldg(&Hh[sb_]));                   \
        float2 v1_ = __half22float2(__ldg(&Hh[sb_ + 32]));              \
        float2 v2_ = __half22float2(__ldg(&Hh[sb_ + 64]));              \
        a0x += w_ * v0_.x; a0y += w_ * v0_.y;                           \
        a1x += w_ * v1_.x; a1y += w_ * v1_.y;                           \
        a2x += w_ * v2_.x; a2y += w_ * v2_.y;                           \
    }

template <int FINAL>
__global__ void __launch_bounds__(256) k_agg(const float* __restrict__ bias,
                                             float* __restrict__ out,
                                             int nodeStart, int nodeCnt) {
    int warp = threadIdx.x >> 5;
    int lane = threadIdx.x & 31;
    int nidx = blockIdx.x * 8 + warp;
    if (nidx >= nodeCnt) return;
    int node = nodeStart + nidx;

    const __half2* Hh = (FINAL == 0) ? g_Hh0 : g_Hh1;

    float dn = g_dinv[node];
    size_t base = (size_t)node * FW2 + lane;

    // self-loop (weight dinv; outer dinv at end -> dinv^2)
    float2 h0 = __half22float2(__ldg(&Hh[base]));
    float2 h1 = __half22float2(__ldg(&Hh[base + 32]));
    float2 h2 = __half22float2(__ldg(&Hh[base + 64]));
    float a0x = dn * h0.x, a0y = dn * h0.y;
    float a1x = dn * h1.x, a1y = dn * h1.y;
    float a2x = dn * h2.x, a2y = dn * h2.y;

    int p = g_rowptr[node];
    int cnt = g_deg[node];

    int j = 0;
    for (; j + 8 <= cnt; j += 8) {
        int2 e0 = __ldg(&g_edges[p + j]);
        int2 e1 = __ldg(&g_edges[p + j + 1]);
        int2 e2 = __ldg(&g_edges[p + j + 2]);
        int2 e3 = __ldg(&g_edges[p + j + 3]);
        int2 e4 = __ldg(&g_edges[p + j + 4]);
        int2 e5 = __ldg(&g_edges[p + j + 5]);
        int2 e6 = __ldg(&g_edges[p + j + 6]);
        int2 e7 = __ldg(&g_edges[p + j + 7]);
        AGG_STEP(e0); AGG_STEP(e1); AGG_STEP(e2); AGG_STEP(e3);
        AGG_STEP(e4); AGG_STEP(e5); AGG_STEP(e6); AGG_STEP(e7);
    }
    for (; j < cnt; ++j) {
        int2 e = __ldg(&g_edges[p + j]);
        AGG_STEP(e);
    }

    float bx = __ldg(&bias[2 * lane]);
    float by = __ldg(&bias[2 * lane + 1]);
    float2 o0 = make_float2(a0x * dn + bx, a0y * dn + by);
    float2 o1 = make_float2(a1x * dn + bx, a1y * dn + by);
    float2 o2 = make_float2(a2x * dn + bx, a2y * dn + by);

    if (FINAL) {
        const float inv3 = 1.f / 3.f;
        int itm = (node >= NU) ? 1 : 0;
        int r = node - itm * NU;
        float2* O2 = (float2*)out;
        float2 x00 = __half22float2(g_X0h[base]);
        float2 x01 = __half22float2(g_X0h[base + 32]);
        float2 x02 = __half22float2(g_X0h[base + 64]);
        float2 x10 = __half22float2(g_Xh[base]);
        float2 x11 = __half22float2(g_Xh[base + 32]);
        float2 x12 = __half22float2(g_Xh[base + 64]);
        float2 r0 = make_float2((x00.x + x10.x + o0.x) * inv3, (x00.y + x10.y + o0.y) * inv3);
        float2 r1 = make_float2((x01.x + x11.x + o1.x) * inv3, (x01.y + x11.y + o1.y) * inv3);
        float2 r2 = make_float2((x02.x + x12.x + o2.x) * inv3, (x02.y + x12.y + o2.y) * inv3);
        __stcs(&O2[(size_t)(0 + itm) * (NU * 32) + (size_t)r * 32 + lane], r0);
        __stcs(&O2[(size_t)(2 + itm) * (NU * 32) + (size_t)r * 32 + lane], r1);
        __stcs(&O2[(size_t)(4 + itm) * (NU * 32) + (size_t)r * 32 + lane], r2);
    } else {
        g_Xh[base]      = __floats2half2_rn(o0.x, o0.y);
        g_Xh[base + 32] = __floats2half2_rn(o1.x, o1.y);
        g_Xh[base + 64] = __floats2half2_rn(o2.x, o2.y);
    }
}

// ---------------- launch ------------------------------------------------------
extern "C" void kernel_launch(void* const* d_in, const int* in_sizes, int n_in,
                              void* d_out, int out_size) {
    const int* ei = (const int*)d_in[0];
    const float* v_feat = (const float*)d_in[1];
    const float* t_feat = (const float*)d_in[2];
    const float* user_emb = (const float*)d_in[3];
    const float* item_emb = (const float*)d_in[4];
    const float* user_emb_v = (const float*)d_in[5];
    const float* user_emb_t = (const float*)d_in[6];
    const float* W_v = (const float*)d_in[7];
    const float* b_v = (const float*)d_in[8];
    const float* W_t = (const float*)d_in[9];
    const float* b_t = (const float*)d_in[10];
    const float* W0 = (const float*)d_in[11];
    const float* b0 = (const float*)d_in[12];
    const float* W1 = (const float*)d_in[13];
    const float* b1 = (const float*)d_in[14];
    float* out = (float*)d_out;

    int E = in_sizes[0] / 2;
    if (E > EMAX) E = EMAX;

    // lazy infra (created on the uncaptured correctness call; reused thereafter)
    static cudaStream_t sT = nullptr, sG = nullptr;
    static cudaEvent_t evRoot = nullptr, evT = nullptr, evG = nullptr;
    static cudaEvent_t evA0A = nullptr, evD1A = nullptr;
    if (sT == nullptr) {
        cudaStreamCreateWithFlags(&sT, cudaStreamNonBlocking);
        cudaStreamCreateWithFlags(&sG, cudaStreamNonBlocking);
        cudaEventCreateWithFlags(&evRoot, cudaEventDisableTiming);
        cudaEventCreateWithFlags(&evT, cudaEventDisableTiming);
        cudaEventCreateWithFlags(&evG, cudaEventDisableTiming);
        cudaEventCreateWithFlags(&evA0A, cudaEventDisableTiming);
        cudaEventCreateWithFlags(&evD1A, cudaEventDisableTiming);
    }

    // fork side streams off the main (capture) stream
    cudaEventRecord(evRoot, 0);
    cudaStreamWaitEvent(sG, evRoot, 0);
    cudaStreamWaitEvent(sT, evRoot, 0);

    // sG: graph build (independent of everything else)
    k_deg_zero<<<(NN + 255) / 256, 256, 0, sG>>>();
    k_count<<<(E + 255) / 256, 256, 0, sG>>>(ei, E);
    k_scan1<<<NB_SCAN, 512, 0, sG>>>();
    k_scan2<<<1, 256, 0, sG>>>();
    k_scan3<<<NB_SCAN, 512, 0, sG>>>();
    k_fill<<<(E + 255) / 256, 256, 0, sG>>>(ei, E);
    cudaEventRecord(evG, sG);

    // sT: initX -> t projection -> dense-L0 user rows (all only need initX)
    k_initX<<<(NU * 32 + 255) / 256, 256, 0, sT>>>(user_emb, user_emb_v, user_emb_t, item_emb);
    k_wgemm_proj<1><<<(NU + 127) / 128, 256, 0, sT>>>(t_feat, NU, 768, W_t, b_t);
    k_wgemm_dense<0><<<DSPLIT / 128, 256, 0, sT>>>(W0, 0);
    cudaEventRecord(evT, sT);

    // main: v projection (big one) runs immediately
    k_wgemm_proj<0><<<(NU + 127) / 128, 256>>>(v_feat, NU, 2048, W_v, b_v);

    // join sT, then dense-L0 item rows
    cudaStreamWaitEvent(0, evT, 0);
    k_wgemm_dense<0><<<(3 * NN - DSPLIT + 127) / 128, 256>>>(W0, DSPLIT);

    // join graph build, then aggregate layer 0 (first half: nodes [0, NA))
    cudaStreamWaitEvent(0, evG, 0);
    k_agg<0><<<(NA + 7) / 8, 256>>>(b0, nullptr, 0, NA);
    cudaEventRecord(evA0A, 0);

    // sT: dense-L1 part A (rows [0, DSPLIT) -> nodes < 50000, final after agg0 A;
    //     writes g_Hh1 — no conflict with agg0 part B which reads g_Hh0)
    cudaStreamWaitEvent(sT, evA0A, 0);
    k_wgemm_dense<1><<<DSPLIT / 128, 256, 0, sT>>>(W1, 0);
    cudaEventRecord(evD1A, sT);

    // main: agg layer 0 second half (nodes [NA, NN)) — overlaps dense-L1 part A
    k_agg<0><<<(NN - NA + 7) / 8, 256>>>(b0, nullptr, NA, NN - NA);

    // join, dense-L1 part B, then final aggregation (fused output)
    cudaStreamWaitEvent(0, evD1A, 0);
    k_wgemm_dense<1><<<(3 * NN - DSPLIT + 127) / 128, 256>>>(W1, DSPLIT);
    k_agg<1><<<(NN + 7) / 8, 256>>>(b1, out, 0, NN);
}